// round 11
// baseline (speedup 1.0000x reference)
#include <cuda_runtime.h>
#include <math.h>

#define BB 256
#define QQ 300
#define GG 16
#define KMAX 10   // ceil(QQ/32) columns per lane
#define NTHR 320  // one q per thread in phase 1; 10 warps

#define PH_FLOATS (QQ * 9)    // 2700
#define PR_FLOATS (QQ * 13)   // 3900
#define PT_FLOATS (QQ * 2)    // 600
#define STAGE_FLOATS (PH_FLOATS + PR_FLOATS + PT_FLOATS)   // 7200
#define STAGE_BYTES (STAGE_FLOATS * 4)                      // 28800
#define DYN_BYTES ((STAGE_FLOATS + GG * QQ) * 4)            // 48000

// ---------------- device scratch (no allocations allowed) ----------------
__device__ double   g_l1[BB];             // per-batch selected-cost sum
__device__ double   g_bce[BB];            // per-batch weighted BCE sum
__device__ int      g_cnt[BB];            // per-batch nval
__device__ unsigned g_done = 0;           // done-counter (last block resets to 0)

__constant__ float c_tw[32] = {
    1.17236407f, 1.0166286f, 1.19620973f, 0.5544405f, 0.63531401f, 0.51258428f,
    1.08866652f, 1.15795989f, 1.07389395f, 0.98728399f, 1.12754142f, 1.05953744f,
    1.16945323f, 1.15512349f, 1.02097204f, 1.15795989f, 1.07147279f, 0.50627649f,
    1.07147279f, 0.61697221f, 1.16367678f, 1.0231585f, 1.18416106f, 1.04329092f,
    1.10645159f, 1.18416106f, 1.15795989f, 1.16367678f, 0.73949534f, 0.78760821f,
    1.08617476f, 1.00805777f
};

// order-preserving float <-> u32 key (finite + inf safe)
__device__ __forceinline__ unsigned f2key(float f) {
    unsigned u = __float_as_uint(f);
    return (u & 0x80000000u) ? ~u : (u | 0x80000000u);
}
__device__ __forceinline__ float key2f(unsigned k) {
    unsigned u = (k & 0x80000000u) ? (k & 0x7fffffffu) : ~k;
    return __uint_as_float(u);
}

// warp argmin (value, lowest index among minima)
__device__ __forceinline__ void warp_argmin(float val, int idx, float& mval, int& midx) {
    const unsigned mykey = f2key(val);
    const unsigned mkey  = __reduce_min_sync(0xffffffffu, mykey);
    const unsigned cand  = (mykey == mkey) ? (unsigned)idx : 0xffffffffu;
    midx = (int)__reduce_min_sync(0xffffffffu, cand);
    mval = key2f(mkey);
}

__device__ __forceinline__ unsigned smem_u32(const void* p) {
    return (unsigned)__cvta_generic_to_shared(p);
}

// ---- fused kernel ----
__global__ __launch_bounds__(NTHR) void fused_kernel(
    const float* __restrict__ ph,
    const float* __restrict__ pr,
    const float* __restrict__ pt,
    const float* __restrict__ IVT,
    const int* __restrict__ iid,
    const int* __restrict__ vid,
    const int* __restrict__ tgt,
    const int* __restrict__ triplet,
    const int* __restrict__ mask,
    float* __restrict__ out)
{
    const int b   = blockIdx.x;
    const int tid = threadIdx.x;
    const int wid = tid >> 5;

    extern __shared__ float dyn[];
    float* s_ph = dyn;                    // [QQ*9]
    float* s_pr = dyn + PH_FLOATS;        // [QQ*13]
    float* s_pt = dyn + PH_FLOATS + PR_FLOATS;  // [QQ*2]
    float* Cm   = dyn + STAGE_FLOATS;     // [GG][QQ] row-major

    __shared__ float s_u[GG + 1];
    __shared__ int   s_p[QQ + 1];
    __shared__ int   s_way[QQ + 1];
    __shared__ int   si[GG], sv[GG], st[GG];
    __shared__ int   s_unass[GG];
    __shared__ float s_rmin[GG];
    __shared__ int   s_jm[GG];
    __shared__ __align__(8) unsigned long long s_mbar;

    // ---- phase -1: one thread kicks off bulk async copies of this block's slices ----
    if (tid == 0) {
        unsigned mbar = smem_u32(&s_mbar);
        asm volatile("mbarrier.init.shared.b64 [%0], %1;" :: "r"(mbar), "r"(1) : "memory");
        asm volatile("fence.proxy.async.shared::cta;" ::: "memory");
        asm volatile("mbarrier.arrive.expect_tx.shared.b64 _, [%0], %1;"
                     :: "r"(mbar), "r"((unsigned)STAGE_BYTES) : "memory");
        asm volatile("cp.async.bulk.shared::cta.global.mbarrier::complete_tx::bytes [%0], [%1], %2, [%3];"
                     :: "r"(smem_u32(s_ph)), "l"(ph + (size_t)b * PH_FLOATS),
                        "r"((unsigned)(PH_FLOATS * 4)), "r"(mbar) : "memory");
        asm volatile("cp.async.bulk.shared::cta.global.mbarrier::complete_tx::bytes [%0], [%1], %2, [%3];"
                     :: "r"(smem_u32(s_pr)), "l"(pr + (size_t)b * PR_FLOATS),
                        "r"((unsigned)(PR_FLOATS * 4)), "r"(mbar) : "memory");
        asm volatile("cp.async.bulk.shared::cta.global.mbarrier::complete_tx::bytes [%0], [%1], %2, [%3];"
                     :: "r"(smem_u32(s_pt)), "l"(pt + (size_t)b * PT_FLOATS),
                        "r"((unsigned)(PT_FLOATS * 4)), "r"(mbar) : "memory");
    }

    // ---- phase 0: warp 0 computes this batch row's weighted BCE (overlapped) ----
    double bce_row = 0.0;
    if (tid < 32) {
        float x = IVT[b * 32 + tid];
        float t = (float)triplet[b * 32 + tid];
        float v = fmaxf(x, 0.f) - x * t + log1pf(expf(-fabsf(x)));
        bce_row = (double)(c_tw[tid] * v);
#pragma unroll
        for (int off = 16; off > 0; off >>= 1)
            bce_row += __shfl_down_sync(0xffffffffu, bce_row, off);
    }

    if (tid < GG) {
        si[tid] = iid[b * GG + tid];
        sv[tid] = vid[b * GG + tid];
        st[tid] = tgt[b * GG + tid];
    }
    for (int j = tid; j <= QQ; j += NTHR) { s_p[j] = 0; s_way[j] = 0; }
    if (tid <= GG) s_u[tid] = 0.f;
    __syncthreads();   // orders mbarrier init for all threads; overlaps with copies

    // wait for the bulk copies (phase parity 0; fresh mbarrier per launch)
    {
        unsigned mbar = smem_u32(&s_mbar);
        unsigned done;
        asm volatile(
            "{\n\t.reg .pred p;\n\t"
            "mbarrier.try_wait.parity.acquire.cta.shared::cta.b64 p, [%1], %2;\n\t"
            "selp.b32 %0, 1, 0, p;\n\t}"
            : "=r"(done) : "r"(mbar), "r"(0u) : "memory");
        if (!done) {
            asm volatile(
                "{\n\t.reg .pred P1;\n\t"
                "WL_%=:\n\t"
                "mbarrier.try_wait.parity.acquire.cta.shared::cta.b64 P1, [%0], %1, 0x989680;\n\t"
                "@P1 bra.uni WD_%=;\n\t"
                "bra.uni WL_%=;\n\t"
                "WD_%=:\n\t}"
                :: "r"(mbar), "r"(0u) : "memory");
        }
    }

    // ---- phase 1: cost matrix from shared (one q per thread) ----
    if (tid < QQ) {
        const int q = tid;
        float h[9], r[13], t[2];
        const float* hp = s_ph + q * 9;
        const float* rp = s_pr + q * 13;
        const float* tp = s_pt + q * 2;

        float mh = -INFINITY, mr = -INFINITY, mt = -INFINITY;
#pragma unroll
        for (int i = 0; i < 9; i++)  { h[i] = hp[i]; mh = fmaxf(mh, h[i]); }
#pragma unroll
        for (int i = 0; i < 13; i++) { r[i] = rp[i]; mr = fmaxf(mr, r[i]); }
#pragma unroll
        for (int i = 0; i < 2; i++)  { t[i] = tp[i]; mt = fmaxf(mt, t[i]); }

        float sh = 0.f, sr = 0.f, stt = 0.f;
#pragma unroll
        for (int i = 0; i < 9; i++)  sh  += expf(h[i] - mh);
#pragma unroll
        for (int i = 0; i < 13; i++) sr  += expf(r[i] - mr);
#pragma unroll
        for (int i = 0; i < 2; i++)  stt += expf(t[i] - mt);

        float lh = mh + logf(sh);
        float lr = mr + logf(sr);
        float lt = mt + logf(stt);

#pragma unroll
        for (int g = 0; g < GG; g++) {
            Cm[g * QQ + q] = (lh - h[si[g]]) + (lr - r[sv[g]]) + (lt - t[st[g]]);
        }
    }
    __syncthreads();

    // ---- phase 1b: all 10 warps compute row minima in parallel ----
    {
        const int lane = tid & 31;
#pragma unroll
        for (int rr = 0; rr < 2; rr++) {
            const int row = wid + 10 * rr;      // rows 0..15 covered by warps 0..9
            if (row < GG) {
                const float* Crow = Cm + row * QQ;
                float best = INFINITY;
                int   bidx = QQ + 2;
#pragma unroll
                for (int k = 0; k < KMAX; k++) {
                    int j = 1 + lane + 32 * k;
                    if (j <= QQ) {
                        float c = Crow[j - 1];
                        if (c < best) { best = c; bidx = j; }
                    }
                }
                float rmin; int jm;
                warp_argmin(best, bidx, rmin, jm);
                if (lane == 0) { s_rmin[row] = rmin; s_jm[row] = jm; }
            }
        }
    }
    __syncthreads();

    // ---- phase 2: warp 0 solves the LAP ----
    if (tid >= 32) return;
    const int lane = tid;

    unsigned mb = __ballot_sync(0xffffffffu, lane < GG && mask[b * GG + lane] != 0);
    const int n = __popc(mb);

    float v[KMAX], minv[KMAX];
#pragma unroll
    for (int k = 0; k < KMAX; k++) v[k] = 0.f;

    // -- phase 2a: greedy init from precomputed row minima --
    int n_unass = 0;
    if (lane == 0) {
        for (int i = 1; i <= n; i++) {
            s_u[i] = s_rmin[i - 1];
            int jm = s_jm[i - 1];
            if (s_p[jm] == 0) s_p[jm] = i;
            else              s_unass[n_unass++] = i;
        }
    }
    n_unass = __shfl_sync(0xffffffffu, n_unass, 0);
    __syncwarp();

    // -- phase 2b: Dijkstra augmentation for unassigned rows only --
    for (int ui = 0; ui < n_unass; ui++) {
        const int i = s_unass[ui];
#pragma unroll
        for (int k = 0; k < KMAX; k++) minv[k] = INFINITY;
        unsigned used = 0;
        int j0 = 0;
        if (lane == 0) s_p[0] = i;
        __syncwarp();

        while (true) {
            if (j0 > 0 && (((j0 - 1) & 31) == lane))
                used |= 1u << ((j0 - 1) >> 5);

            const int   i0   = s_p[j0];
            const float u_i0 = s_u[i0];
            const float* Crow = Cm + (i0 - 1) * QQ;

            float best = INFINITY;
            int   bidx = QQ + 2;
#pragma unroll
            for (int k = 0; k < KMAX; k++) {
                int j = 1 + lane + 32 * k;
                if (j <= QQ && !((used >> k) & 1u)) {
                    float cur = Crow[j - 1] - u_i0 - v[k];
                    if (cur < minv[k]) { minv[k] = cur; s_way[j] = j0; }
                    if (minv[k] < best) { best = minv[k]; bidx = j; }
                }
            }
            float delta; int j1;
            warp_argmin(best, bidx, delta, j1);

#pragma unroll
            for (int k = 0; k < KMAX; k++) {
                int j = 1 + lane + 32 * k;
                if (j <= QQ) {
                    if ((used >> k) & 1u) {
                        v[k] -= delta;
                        s_u[s_p[j]] += delta;     // distinct p[j] across used cols
                    } else {
                        minv[k] -= delta;
                    }
                }
            }
            if (lane == 0) s_u[i] += delta;       // virtual column 0 (p[0] = i)
            __syncwarp();

            if (s_p[j1] == 0) { j0 = j1; break; }
            j0 = j1;
        }

        // augment alternating path
        if (lane == 0) {
            int jj = j0;
            while (jj) {
                int jp = s_way[jj];
                s_p[jj] = s_p[jp];
                jj = jp;
            }
        }
        __syncwarp();
    }

    // sum selected float32 costs (optimal total is assignment-independent)
    double local = 0.0;
#pragma unroll
    for (int k = 0; k < KMAX; k++) {
        int j = 1 + lane + 32 * k;
        if (j <= QQ) {
            int pj = s_p[j];
            if (pj > 0) local += (double)Cm[(pj - 1) * QQ + (j - 1)];
        }
    }
#pragma unroll
    for (int off = 16; off > 0; off >>= 1)
        local += __shfl_down_sync(0xffffffffu, local, off);
    if (lane == 0) {
        g_l1[b]  = local;
        g_cnt[b] = n;
        g_bce[b] = bce_row;
    }

    // ---- phase 3: last block performs the final combine (deterministic order) ----
    __threadfence();
    unsigned old = 0;
    if (lane == 0) old = atomicAdd(&g_done, 1u);
    old = __shfl_sync(0xffffffffu, old, 0);
    if (old == BB - 1) {
        double l1 = 0.0, cnt = 0.0, bce = 0.0;
#pragma unroll
        for (int k = 0; k < BB / 32; k++) {
            int bb = lane + 32 * k;
            l1  += __ldcg(&g_l1[bb]);
            cnt += (double)__ldcg(&g_cnt[bb]);
            bce += __ldcg(&g_bce[bb]);
        }
#pragma unroll
        for (int off = 16; off > 0; off >>= 1) {
            l1  += __shfl_down_sync(0xffffffffu, l1, off);
            cnt += __shfl_down_sync(0xffffffffu, cnt, off);
            bce += __shfl_down_sync(0xffffffffu, bce, off);
        }
        if (lane == 0) {
            double loss1 = l1 / cnt;
            double loss5 = bce / (double)(BB * 32);
            out[0] = (float)(0.1 * loss1 + 1.0 * loss5);
            g_done = 0;                      // reset for next graph replay
        }
    }
}

// ---------------- launch ----------------
extern "C" void kernel_launch(void* const* d_in, const int* in_sizes, int n_in,
                              void* d_out, int out_size) {
    const float* pred_head = (const float*)d_in[0];
    const float* pred_rel  = (const float*)d_in[1];
    const float* pred_tail = (const float*)d_in[2];
    const float* IVT       = (const float*)d_in[3];
    const int*   iid       = (const int*)d_in[4];
    const int*   vid       = (const int*)d_in[5];
    const int*   tgt       = (const int*)d_in[6];
    // d_in[7..9] (instrument, verb, target) unused by the reference
    const int*   triplet   = (const int*)d_in[10];
    const int*   mask      = (const int*)d_in[11];
    float* out = (float*)d_out;

    static bool attr_set = false;
    if (!attr_set) {
        cudaFuncSetAttribute(fused_kernel,
                             cudaFuncAttributeMaxDynamicSharedMemorySize, DYN_BYTES);
        attr_set = true;
    }

    fused_kernel<<<BB, NTHR, DYN_BYTES>>>(pred_head, pred_rel, pred_tail, IVT,
                                          iid, vid, tgt, triplet, mask, out);
}

// round 12
// speedup vs baseline: 1.1525x; 1.1525x over previous
#include <cuda_runtime.h>
#include <math.h>

#define BB 256
#define QQ 300
#define GG 16
#define KMAX 10   // ceil(QQ/32) columns per lane
#define NTHR 320  // one q per thread in phase 1; 10 warps

#define SCR_W 25                           // 24 logits + lsum, stride 25 (coprime to 32)
#define DYN_FLOATS (QQ * SCR_W + GG * QQ)  // 7500 + 4800 = 12300
#define DYN_BYTES (DYN_FLOATS * 4)         // 49200

// ---------------- device scratch (no allocations allowed) ----------------
__device__ double   g_l1[BB];             // per-batch selected-cost sum
__device__ double   g_bce[BB];            // per-batch weighted BCE sum
__device__ int      g_cnt[BB];            // per-batch nval
__device__ unsigned g_done = 0;           // done-counter (last block resets to 0)

__constant__ float c_tw[32] = {
    1.17236407f, 1.0166286f, 1.19620973f, 0.5544405f, 0.63531401f, 0.51258428f,
    1.08866652f, 1.15795989f, 1.07389395f, 0.98728399f, 1.12754142f, 1.05953744f,
    1.16945323f, 1.15512349f, 1.02097204f, 1.15795989f, 1.07147279f, 0.50627649f,
    1.07147279f, 0.61697221f, 1.16367678f, 1.0231585f, 1.18416106f, 1.04329092f,
    1.10645159f, 1.18416106f, 1.15795989f, 1.16367678f, 0.73949534f, 0.78760821f,
    1.08617476f, 1.00805777f
};

// order-preserving float <-> u32 key (finite + inf safe)
__device__ __forceinline__ unsigned f2key(float f) {
    unsigned u = __float_as_uint(f);
    return (u & 0x80000000u) ? ~u : (u | 0x80000000u);
}
__device__ __forceinline__ float key2f(unsigned k) {
    unsigned u = (k & 0x80000000u) ? (k & 0x7fffffffu) : ~k;
    return __uint_as_float(u);
}

// warp argmin (value, lowest index among minima)
__device__ __forceinline__ void warp_argmin(float val, int idx, float& mval, int& midx) {
    const unsigned mykey = f2key(val);
    const unsigned mkey  = __reduce_min_sync(0xffffffffu, mykey);
    const unsigned cand  = (mykey == mkey) ? (unsigned)idx : 0xffffffffu;
    midx = (int)__reduce_min_sync(0xffffffffu, cand);
    mval = key2f(mkey);
}

// ---- fused kernel ----
__global__ __launch_bounds__(NTHR) void fused_kernel(
    const float* __restrict__ ph,
    const float* __restrict__ pr,
    const float* __restrict__ pt,
    const float* __restrict__ IVT,
    const int* __restrict__ iid,
    const int* __restrict__ vid,
    const int* __restrict__ tgt,
    const int* __restrict__ triplet,
    const int* __restrict__ mask,
    float* __restrict__ out)
{
    const int b   = blockIdx.x;
    const int tid = threadIdx.x;
    const int wid = tid >> 5;

    extern __shared__ float dyn[];
    float* s_scr = dyn;                  // [QQ][SCR_W]: 0..8 h, 9..21 r, 22..23 t, 24 lsum
    float* Cm    = dyn + QQ * SCR_W;     // [GG][QQ] row-major

    __shared__ float s_u[GG + 1];
    __shared__ int   s_p[QQ + 1];
    __shared__ int   s_way[QQ + 1];
    __shared__ int   si[GG], sv[GG], st[GG];
    __shared__ int   s_unass[GG];
    __shared__ float s_rmin[GG];
    __shared__ int   s_jm[GG];

    // ---- phase 0: warp 0 computes this batch row's weighted BCE (overlapped) ----
    double bce_row = 0.0;
    if (tid < 32) {
        float x = IVT[b * 32 + tid];
        float t = (float)triplet[b * 32 + tid];
        float v = fmaxf(x, 0.f) - x * t + log1pf(__expf(-fabsf(x)));
        bce_row = (double)(c_tw[tid] * v);
#pragma unroll
        for (int off = 16; off > 0; off >>= 1)
            bce_row += __shfl_down_sync(0xffffffffu, bce_row, off);
    }

    if (tid < GG) {
        si[tid] = iid[b * GG + tid];
        sv[tid] = vid[b * GG + tid];
        st[tid] = tgt[b * GG + tid];
    }
    for (int j = tid; j <= QQ; j += NTHR) { s_p[j] = 0; s_way[j] = 0; }
    if (tid <= GG) s_u[tid] = 0.f;
    __syncthreads();

    // ---- phase 1: logits -> shared scratch + direct log-sum-exp (no max chain,
    //      no dynamic register indexing -> no local-memory spills) ----
    if (tid < QQ) {
        const int q = tid;
        float* scr = s_scr + q * SCR_W;
        const float* hp = ph + (size_t)(b * QQ + q) * 9;
        const float* rp = pr + (size_t)(b * QQ + q) * 13;
        const float* tp = pt + (size_t)(b * QQ + q) * 2;

        float sh = 0.f, sr = 0.f, stt = 0.f;
#pragma unroll
        for (int i = 0; i < 9; i++)  { float x = hp[i]; scr[i]      = x; sh  += __expf(x); }
#pragma unroll
        for (int i = 0; i < 13; i++) { float x = rp[i]; scr[9 + i]  = x; sr  += __expf(x); }
#pragma unroll
        for (int i = 0; i < 2; i++)  { float x = tp[i]; scr[22 + i] = x; stt += __expf(x); }

        const float lsum = __logf(sh) + __logf(sr) + __logf(stt);
        scr[24] = lsum;

        // gather costs via LDS (si/sv/st are warp-uniform per g; stride-25 rows -> conflict-free)
#pragma unroll
        for (int g = 0; g < GG; g++) {
            Cm[g * QQ + q] = lsum - (scr[si[g]] + scr[9 + sv[g]] + scr[22 + st[g]]);
        }
    }
    __syncthreads();

    // ---- phase 1b: all 10 warps compute row minima in parallel ----
    {
        const int lane = tid & 31;
#pragma unroll
        for (int rr = 0; rr < 2; rr++) {
            const int row = wid + 10 * rr;      // rows 0..15 covered by warps 0..9
            if (row < GG) {
                const float* Crow = Cm + row * QQ;
                float best = INFINITY;
                int   bidx = QQ + 2;
#pragma unroll
                for (int k = 0; k < KMAX; k++) {
                    int j = 1 + lane + 32 * k;
                    if (j <= QQ) {
                        float c = Crow[j - 1];
                        if (c < best) { best = c; bidx = j; }
                    }
                }
                float rmin; int jm;
                warp_argmin(best, bidx, rmin, jm);
                if (lane == 0) { s_rmin[row] = rmin; s_jm[row] = jm; }
            }
        }
    }
    __syncthreads();

    // ---- phase 2: warp 0 solves the LAP ----
    if (tid >= 32) return;
    const int lane = tid;

    unsigned mb = __ballot_sync(0xffffffffu, lane < GG && mask[b * GG + lane] != 0);
    const int n = __popc(mb);

    float v[KMAX], minv[KMAX];
#pragma unroll
    for (int k = 0; k < KMAX; k++) v[k] = 0.f;

    // -- phase 2a: greedy init from precomputed row minima --
    int n_unass = 0;
    if (lane == 0) {
        for (int i = 1; i <= n; i++) {
            s_u[i] = s_rmin[i - 1];
            int jm = s_jm[i - 1];
            if (s_p[jm] == 0) s_p[jm] = i;
            else              s_unass[n_unass++] = i;
        }
    }
    n_unass = __shfl_sync(0xffffffffu, n_unass, 0);
    __syncwarp();

    // -- phase 2b: Dijkstra augmentation for unassigned rows only --
    for (int ui = 0; ui < n_unass; ui++) {
        const int i = s_unass[ui];
#pragma unroll
        for (int k = 0; k < KMAX; k++) minv[k] = INFINITY;
        unsigned used = 0;
        int j0 = 0;
        if (lane == 0) s_p[0] = i;
        __syncwarp();

        while (true) {
            if (j0 > 0 && (((j0 - 1) & 31) == lane))
                used |= 1u << ((j0 - 1) >> 5);

            const int   i0   = s_p[j0];
            const float u_i0 = s_u[i0];
            const float* Crow = Cm + (i0 - 1) * QQ;

            float best = INFINITY;
            int   bidx = QQ + 2;
#pragma unroll
            for (int k = 0; k < KMAX; k++) {
                int j = 1 + lane + 32 * k;
                if (j <= QQ && !((used >> k) & 1u)) {
                    float cur = Crow[j - 1] - u_i0 - v[k];
                    if (cur < minv[k]) { minv[k] = cur; s_way[j] = j0; }
                    if (minv[k] < best) { best = minv[k]; bidx = j; }
                }
            }
            float delta; int j1;
            warp_argmin(best, bidx, delta, j1);

#pragma unroll
            for (int k = 0; k < KMAX; k++) {
                int j = 1 + lane + 32 * k;
                if (j <= QQ) {
                    if ((used >> k) & 1u) {
                        v[k] -= delta;
                        s_u[s_p[j]] += delta;     // distinct p[j] across used cols
                    } else {
                        minv[k] -= delta;
                    }
                }
            }
            if (lane == 0) s_u[i] += delta;       // virtual column 0 (p[0] = i)
            __syncwarp();

            if (s_p[j1] == 0) { j0 = j1; break; }
            j0 = j1;
        }

        // augment alternating path
        if (lane == 0) {
            int jj = j0;
            while (jj) {
                int jp = s_way[jj];
                s_p[jj] = s_p[jp];
                jj = jp;
            }
        }
        __syncwarp();
    }

    // sum selected float32 costs (optimal total is assignment-independent)
    double local = 0.0;
#pragma unroll
    for (int k = 0; k < KMAX; k++) {
        int j = 1 + lane + 32 * k;
        if (j <= QQ) {
            int pj = s_p[j];
            if (pj > 0) local += (double)Cm[(pj - 1) * QQ + (j - 1)];
        }
    }
#pragma unroll
    for (int off = 16; off > 0; off >>= 1)
        local += __shfl_down_sync(0xffffffffu, local, off);
    if (lane == 0) {
        g_l1[b]  = local;
        g_cnt[b] = n;
        g_bce[b] = bce_row;
    }

    // ---- phase 3: last block performs the final combine (deterministic order) ----
    __threadfence();
    unsigned old = 0;
    if (lane == 0) old = atomicAdd(&g_done, 1u);
    old = __shfl_sync(0xffffffffu, old, 0);
    if (old == BB - 1) {
        double l1 = 0.0, cnt = 0.0, bce = 0.0;
#pragma unroll
        for (int k = 0; k < BB / 32; k++) {
            int bb = lane + 32 * k;
            l1  += __ldcg(&g_l1[bb]);
            cnt += (double)__ldcg(&g_cnt[bb]);
            bce += __ldcg(&g_bce[bb]);
        }
#pragma unroll
        for (int off = 16; off > 0; off >>= 1) {
            l1  += __shfl_down_sync(0xffffffffu, l1, off);
            cnt += __shfl_down_sync(0xffffffffu, cnt, off);
            bce += __shfl_down_sync(0xffffffffu, bce, off);
        }
        if (lane == 0) {
            double loss1 = l1 / cnt;
            double loss5 = bce / (double)(BB * 32);
            out[0] = (float)(0.1 * loss1 + 1.0 * loss5);
            g_done = 0;                      // reset for next graph replay
        }
    }
}

// ---------------- launch ----------------
extern "C" void kernel_launch(void* const* d_in, const int* in_sizes, int n_in,
                              void* d_out, int out_size) {
    const float* pred_head = (const float*)d_in[0];
    const float* pred_rel  = (const float*)d_in[1];
    const float* pred_tail = (const float*)d_in[2];
    const float* IVT       = (const float*)d_in[3];
    const int*   iid       = (const int*)d_in[4];
    const int*   vid       = (const int*)d_in[5];
    const int*   tgt       = (const int*)d_in[6];
    // d_in[7..9] (instrument, verb, target) unused by the reference
    const int*   triplet   = (const int*)d_in[10];
    const int*   mask      = (const int*)d_in[11];
    float* out = (float*)d_out;

    static bool attr_set = false;
    if (!attr_set) {
        cudaFuncSetAttribute(fused_kernel,
                             cudaFuncAttributeMaxDynamicSharedMemorySize, DYN_BYTES);
        attr_set = true;
    }

    fused_kernel<<<BB, NTHR, DYN_BYTES>>>(pred_head, pred_rel, pred_tail, IVT,
                                          iid, vid, tgt, triplet, mask, out);
}